// round 10
// baseline (speedup 1.0000x reference)
#include <cuda_runtime.h>
#include <cuda_bf16.h>
#include <math.h>
#include <stdint.h>

#define SEQ    2048
#define BATCH  2
#define TOK    4096
#define DIM    1024
#define NHEAD  16
#define KVHEAD 4
#define HDIM   64
#define NLAYER 8
#define FF     4096
#define VOCAB  32000

typedef __nv_bfloat16 bf16;

// ---------------- scratch ----------------
__device__ float g_h   [TOK * DIM];
__device__ float g_qkv [TOK * 1536];          // [q(1024)|k(256)|v(256)]
__device__ float g_f13 [TOK * 8192];          // [f1(4096)|f3(4096)]
__device__ float g_cos [SEQ * 32];
__device__ float g_sin [SEQ * 32];
// expanded bf16 activations (A-operand: [hi|hi|lo])
__device__ bf16 g_xne [TOK * 3072];
__device__ bf16 g_atte[TOK * 3072];
__device__ bf16 g_f1e [TOK * 12288];
// expanded bf16 weights (B-operand: [hi|lo|hi])
__device__ bf16 e_wqkv[NLAYER * 1536 * 3072];
__device__ bf16 e_wo  [NLAYER * 1024 * 3072];
__device__ bf16 e_w13 [NLAYER * 8192 * 3072];
__device__ bf16 e_w2  [NLAYER * 1024 * 12288];
__device__ bf16 e_emb [VOCAB * 3072];

__device__ __forceinline__ void split2(float x, bf16& hi, bf16& lo) {
    hi = __float2bfloat16_rn(x);
    lo = __float2bfloat16_rn(x - __bfloat162float(hi));
}

// ---------------- weight expansion: out rows = [hi | lo | hi] ----------------
__global__ void expand_w_kernel(const float* __restrict__ in, bf16* __restrict__ out,
                                int K, int rows_pl, size_t lstride, int row_off) {
    size_t idx = (size_t)blockIdx.x * 256 + threadIdx.x;
    int rt = (int)(idx / K);
    int k  = (int)(idx % K);
    int l  = rt / rows_pl;
    int r  = rt % rows_pl;
    float x = in[idx];
    bf16 hi, lo; split2(x, hi, lo);
    bf16* o = out + (size_t)l * lstride + (size_t)(row_off + r) * (3 * K);
    o[k] = hi; o[K + k] = lo; o[2 * K + k] = hi;
}

// ---------------- RoPE tables ----------------
__global__ void rope_init_kernel() {
    int t = blockIdx.x, j = threadIdx.x;
    double inv   = pow(10000.0, -(2.0 * j) / 64.0);
    double r     = 81920.0 * inv / (2.0 * M_PI);
    double gamma = (r - 1.0) / 31.0;
    gamma = gamma < 0.0 ? 0.0 : (gamma > 1.0 ? 1.0 : gamma);
    double inv2  = inv * ((1.0 - gamma) / 40.0 + gamma);
    double c     = sqrt(0.1 * log(40.0) + 1.0);
    double ang   = (double)t * inv2 / c;
    g_cos[t * 32 + j] = (float)cos(ang);
    g_sin[t * 32 + j] = (float)sin(ang);
}

__global__ void embed_kernel(const int* __restrict__ ids, const float* __restrict__ emb) {
    int t = blockIdx.x;
    const float* src = emb + (size_t)ids[t] * DIM;
    float* dst = g_h + (size_t)t * DIM;
    for (int d = threadIdx.x; d < DIM; d += blockDim.x) dst[d] = src[d];
}

// ---------------- rmsnorm -> expanded bf16 [hi|hi|lo] ----------------
__global__ __launch_bounds__(256) void rmsnorm_expand_kernel(
    const float* __restrict__ x, const float* __restrict__ w, bf16* __restrict__ o) {
    int row = blockIdx.x, tid = threadIdx.x;
    const float* xr = x + (size_t)row * DIM;
    float s = 0.f;
    for (int d = tid; d < DIM; d += 256) { float v = xr[d]; s += v * v; }
    #pragma unroll
    for (int off = 16; off; off >>= 1) s += __shfl_xor_sync(0xffffffffu, s, off);
    __shared__ float red[8]; __shared__ float rsv;
    if ((tid & 31) == 0) red[tid >> 5] = s;
    __syncthreads();
    if (tid == 0) {
        float t = 0.f;
        #pragma unroll
        for (int i = 0; i < 8; i++) t += red[i];
        rsv = rsqrtf(t / (float)DIM + 1e-6f);
    }
    __syncthreads();
    float rs = rsv;
    bf16* orow = o + (size_t)row * 3072;
    for (int d = tid; d < DIM; d += 256) {
        float y = xr[d] * rs * w[d];
        bf16 hi, lo; split2(y, hi, lo);
        orow[d] = hi; orow[1024 + d] = hi; orow[2048 + d] = lo;
    }
}

// ================= bf16 tensor-core GEMM v2 (2 CTAs/SM) =================
// C[M,N](f32) = Ae[M,K'](bf16) @ We[N,K'](bf16)^T (+R)
// CTA tile 128x128, BK=32 bf16, 256 threads, warp grid 4(M)x2(N),
// warp tile 32x64 = 2 x 8 mma(m16n8k16). 2-stage cp.async, 32KB smem,
// ~110 regs -> 2 CTAs/SM (4 warps/SMSP) for HMMA issue overlap.
#define BM 128
#define BN 128
#define BKE 32
#define A_BYTES (BM * BKE * 2)             // 8192
#define B_BYTES (BN * BKE * 2)             // 8192
#define STAGE_BYTES (A_BYTES + B_BYTES)    // 16384

__device__ __forceinline__ uint32_t swz(uint32_t r, uint32_t kf) {
    return (r * 4u + (kf ^ ((r >> 1) & 3u))) << 4;
}
#define CP_ASYNC16(dst, src) \
    asm volatile("cp.async.cg.shared.global [%0], [%1], 16;" :: "r"(dst), "l"(src))
#define CP_COMMIT()  asm volatile("cp.async.commit_group;")
#define CP_WAIT1()   asm volatile("cp.async.wait_group 1;")
#define LDSM_X4(r0, r1, r2, r3, addr) \
    asm volatile("ldmatrix.sync.aligned.m8n8.x4.shared.b16 {%0,%1,%2,%3}, [%4];" \
        : "=r"(r0), "=r"(r1), "=r"(r2), "=r"(r3) : "r"(addr))
#define MMA_BF16(c, a0, a1, a2, a3, b0, b1) \
    asm volatile("mma.sync.aligned.m16n8k16.row.col.f32.bf16.bf16.f32 " \
        "{%0,%1,%2,%3}, {%4,%5,%6,%7}, {%8,%9}, {%0,%1,%2,%3};" \
        : "+f"(c[0]), "+f"(c[1]), "+f"(c[2]), "+f"(c[3]) \
        : "r"(a0), "r"(a1), "r"(a2), "r"(a3), "r"(b0), "r"(b1))

template <int RES>
__global__ __launch_bounds__(256, 2) void gemm_bf(
    const bf16* __restrict__ A, const bf16* __restrict__ W,
    const float* __restrict__ R, float* __restrict__ C, int N, int K) {
    __shared__ __align__(16) char smem[2 * STAGE_BYTES];   // 32KB
    const int tid  = threadIdx.x;
    const int lane = tid & 31;
    const int wid  = tid >> 5;
    const int wm   = wid >> 1;          // 0..3
    const int wn   = wid & 1;           // 0..1
    const int bm   = blockIdx.y * BM;
    const int bn   = blockIdx.x * BN;
    const uint32_t smem_u = (uint32_t)__cvta_generic_to_shared(smem);

    // ---- gmem -> smem copy assignment: 1024 granules/stage, 4 per thread ----
    // granule g: r = g>>2 (0..127 wait: 512 granules per tile), A gets 512, B gets 512
    const int r0g = tid >> 1;                 // 0..127
    const int k0g = (tid & 1) * 2;            // 0 or 2 (two granules each)
    const bf16* Ag0 = A + (size_t)(bm + r0g) * K + k0g * 8;
    const bf16* Wg0 = W + (size_t)(bn + r0g) * K + k0g * 8;
    const uint32_t aO0 = swz(r0g, k0g), aO1 = swz(r0g, k0g + 1);
    // (second granule of pair is +8 bf16 in gmem)

    // ---- ldmatrix per-lane addresses ----
    const int flr = lane & 15;
    const int fhi = lane >> 4;
    uint32_t a_off[2][2];
    #pragma unroll
    for (int s = 0; s < 2; s++)
        #pragma unroll
        for (int i = 0; i < 2; i++)
            a_off[s][i] = swz(wm * 32 + i * 16 + flr, 2 * s + fhi);
    const int brow_b = wn * 64 + (lane & 7) + fhi * 8;
    const int bkf_h  = (lane >> 3) & 1;
    uint32_t b_off[2][4];
    #pragma unroll
    for (int s = 0; s < 2; s++)
        #pragma unroll
        for (int p = 0; p < 4; p++)
            b_off[s][p] = (uint32_t)A_BYTES + swz(brow_b + p * 16, 2 * s + bkf_h);

    float acc[2][8][4];
    #pragma unroll
    for (int i = 0; i < 2; i++)
        #pragma unroll
        for (int j = 0; j < 8; j++)
            #pragma unroll
            for (int q = 0; q < 4; q++) acc[i][j][q] = 0.f;

    const int nk = K / BKE;
    // prologue: stage 0
    {
        uint32_t base = smem_u;
        CP_ASYNC16(base + aO0, Ag0);
        CP_ASYNC16(base + aO1, Ag0 + 8);
        uint32_t bb = base + A_BYTES;
        CP_ASYNC16(bb + aO0, Wg0);
        CP_ASYNC16(bb + aO1, Wg0 + 8);
        CP_COMMIT();
    }

    for (int kt = 0; kt < nk; kt++) {
        if (kt + 1 < nk) {
            int k0 = (kt + 1) * BKE;
            uint32_t base = smem_u + ((kt + 1) & 1) * STAGE_BYTES;
            CP_ASYNC16(base + aO0, Ag0 + k0);
            CP_ASYNC16(base + aO1, Ag0 + k0 + 8);
            uint32_t bb = base + A_BYTES;
            CP_ASYNC16(bb + aO0, Wg0 + k0);
            CP_ASYNC16(bb + aO1, Wg0 + k0 + 8);
        }
        CP_COMMIT();
        CP_WAIT1();
        __syncthreads();

        uint32_t cbase = smem_u + (kt & 1) * STAGE_BYTES;
        #pragma unroll
        for (int s = 0; s < 2; s++) {
            uint32_t af[2][4];
            #pragma unroll
            for (int i = 0; i < 2; i++)
                LDSM_X4(af[i][0], af[i][1], af[i][2], af[i][3], cbase + a_off[s][i]);
            #pragma unroll
            for (int p = 0; p < 4; p++) {
                uint32_t b0, b1, b2, b3;
                LDSM_X4(b0, b1, b2, b3, cbase + b_off[s][p]);
                #pragma unroll
                for (int i = 0; i < 2; i++) {
                    MMA_BF16(acc[i][2 * p],     af[i][0], af[i][1], af[i][2], af[i][3], b0, b1);
                    MMA_BF16(acc[i][2 * p + 1], af[i][0], af[i][1], af[i][2], af[i][3], b2, b3);
                }
            }
        }
        __syncthreads();
    }

    const int gid = lane >> 2, tig = lane & 3;
    #pragma unroll
    for (int i = 0; i < 2; i++) {
        int r0 = bm + wm * 32 + i * 16 + gid;
        #pragma unroll
        for (int j = 0; j < 8; j++) {
            int c0 = bn + wn * 64 + j * 8 + tig * 2;
            size_t o0 = (size_t)r0 * N + c0;
            size_t o1 = o0 + (size_t)8 * N;
            float2 v0 = make_float2(acc[i][j][0], acc[i][j][1]);
            float2 v1 = make_float2(acc[i][j][2], acc[i][j][3]);
            if (RES) {
                float2 ra = *(const float2*)(R + o0);
                float2 rb = *(const float2*)(R + o1);
                v0.x += ra.x; v0.y += ra.y; v1.x += rb.x; v1.y += rb.y;
            }
            *(float2*)(C + o0) = v0;
            *(float2*)(C + o1) = v1;
        }
    }
}

// ---------------- RoPE on qkv slab ----------------
__global__ void rope_kernel(float* __restrict__ x, int nheads, int off) {
    int idx = blockIdx.x * 256 + threadIdx.x;
    int i  = idx & 31;
    int hh = (idx >> 5) % nheads;
    int t  = idx / (32 * nheads);
    int s  = t & (SEQ - 1);
    float c  = g_cos[s * 32 + i];
    float sn = g_sin[s * 32 + i];
    float* p = x + (size_t)t * 1536 + off + hh * HDIM;
    float x1 = p[i], x2 = p[i + 32];
    p[i]      = x1 * c - x2 * sn;
    p[i + 32] = x2 * c + x1 * sn;
}

// ---------------- causal GQA flash attention (v1: thread-per-query) ---------
__global__ __launch_bounds__(64) void attn_kernel(
    const float* __restrict__ qkv, bf16* __restrict__ oe) {
    __shared__ float Ks[64][64];
    __shared__ float Vs[64][64];
    __shared__ float Ss[64][64];
    int qt = blockIdx.x, h = blockIdx.y, b = blockIdx.z;
    int g = h >> 2;
    int tid = threadIdx.x;
    int qi = qt * 64 + tid;

    const float* qp = qkv + (size_t)(b * SEQ + qi) * 1536 + h * HDIM;
    float qr[64];
    #pragma unroll
    for (int d = 0; d < 64; d += 4) {
        float4 t4 = *(const float4*)(qp + d);
        qr[d] = t4.x * 0.125f; qr[d + 1] = t4.y * 0.125f;
        qr[d + 2] = t4.z * 0.125f; qr[d + 3] = t4.w * 0.125f;
    }
    float m = -1e30f, l = 0.f;
    float acc[64];
    #pragma unroll
    for (int d = 0; d < 64; d++) acc[d] = 0.f;

    for (int j = 0; j <= qt; j++) {
        const float* kp = qkv + (size_t)(b * SEQ + j * 64) * 1536 + 1024 + g * HDIM;
        const float* vp = kp + 256;
        __syncthreads();
        #pragma unroll
        for (int i = 0; i < 16; i++) {
            int idx = i * 64 + tid;
            int r = idx >> 4, c = (idx & 15) * 4;
            *(float4*)&Ks[r][c] = *(const float4*)(kp + (size_t)r * 1536 + c);
            *(float4*)&Vs[r][c] = *(const float4*)(vp + (size_t)r * 1536 + c);
        }
        __syncthreads();
        #pragma unroll
        for (int kk = 0; kk < 64; kk++) {
            float s = 0.f;
            #pragma unroll
            for (int d = 0; d < 64; d += 4) {
                float4 kv = *(const float4*)&Ks[kk][d];
                s += qr[d] * kv.x + qr[d + 1] * kv.y + qr[d + 2] * kv.z + qr[d + 3] * kv.w;
            }
            Ss[kk][tid] = s;
        }
        if (j == qt) {
            for (int kk = tid + 1; kk < 64; kk++) Ss[kk][tid] = -1e30f;
        }
        float tmax = -1e30f;
        #pragma unroll
        for (int kk = 0; kk < 64; kk++) tmax = fmaxf(tmax, Ss[kk][tid]);
        float nm = fmaxf(m, tmax);
        float corr = __expf(m - nm);
        l *= corr;
        #pragma unroll
        for (int d = 0; d < 64; d++) acc[d] *= corr;
        #pragma unroll
        for (int kk = 0; kk < 64; kk++) {
            float p = __expf(Ss[kk][tid] - nm);
            l += p;
            #pragma unroll
            for (int d = 0; d < 64; d += 4) {
                float4 vv = *(const float4*)&Vs[kk][d];
                acc[d]     += p * vv.x; acc[d + 1] += p * vv.y;
                acc[d + 2] += p * vv.z; acc[d + 3] += p * vv.w;
            }
        }
        m = nm;
    }
    float inv = 1.f / l;
    bf16* op = oe + (size_t)(b * SEQ + qi) * 3072 + h * HDIM;
    #pragma unroll
    for (int d = 0; d < 64; d += 2) {
        float y0 = acc[d] * inv, y1 = acc[d + 1] * inv;
        bf16 h0, l0, h1, l1;
        split2(y0, h0, l0); split2(y1, h1, l1);
        *(__nv_bfloat162*)(op + d)        = __nv_bfloat162(h0, h1);
        *(__nv_bfloat162*)(op + 1024 + d) = __nv_bfloat162(h0, h1);
        *(__nv_bfloat162*)(op + 2048 + d) = __nv_bfloat162(l0, l1);
    }
}

// ---------------- SwiGLU -> expanded [hi|hi|lo] ----------------
__global__ void swiglu_expand_kernel() {
    int i = blockIdx.x * 256 + threadIdx.x;   // over TOK*FF
    int t = i >> 12, c = i & 4095;
    float a = g_f13[(size_t)t * 8192 + c];
    float b = g_f13[(size_t)t * 8192 + 4096 + c];
    float u = (a / (1.f + __expf(-a))) * b;
    bf16 hi, lo; split2(u, hi, lo);
    bf16* o = g_f1e + (size_t)t * 12288;
    o[c] = hi; o[4096 + c] = hi; o[8192 + c] = lo;
}

// ---------------- host orchestration ----------------
extern "C" void kernel_launch(void* const* d_in, const int* in_sizes, int n_in,
                              void* d_out, int out_size) {
    const int*   ids = (const int*)d_in[0];
    const float* emb = (const float*)d_in[1];
    const float* wq  = (const float*)d_in[2];
    const float* wk  = (const float*)d_in[3];
    const float* wv  = (const float*)d_in[4];
    const float* wo  = (const float*)d_in[5];
    const float* n1  = (const float*)d_in[6];
    const float* n2  = (const float*)d_in[7];
    const float* w1  = (const float*)d_in[8];
    const float* w2  = (const float*)d_in[9];
    const float* w3  = (const float*)d_in[10];
    const float* fnw = (const float*)d_in[11];
    float* out = (float*)d_out;

    float *h, *qkv, *f13;
    bf16 *xne, *atte, *f1e, *ewqkv, *ewo, *ew13, *ew2, *eemb;
    cudaGetSymbolAddress((void**)&h,     g_h);
    cudaGetSymbolAddress((void**)&qkv,   g_qkv);
    cudaGetSymbolAddress((void**)&f13,   g_f13);
    cudaGetSymbolAddress((void**)&xne,   g_xne);
    cudaGetSymbolAddress((void**)&atte,  g_atte);
    cudaGetSymbolAddress((void**)&f1e,   g_f1e);
    cudaGetSymbolAddress((void**)&ewqkv, e_wqkv);
    cudaGetSymbolAddress((void**)&ewo,   e_wo);
    cudaGetSymbolAddress((void**)&ew13,  e_w13);
    cudaGetSymbolAddress((void**)&ew2,   e_w2);
    cudaGetSymbolAddress((void**)&eemb,  e_emb);

    // ---- expand all weights (bf16 hi/lo triple) ----
    expand_w_kernel<<<(NLAYER * 1024 * 1024) / 256, 256>>>(wq, ewqkv, 1024, 1024, (size_t)1536 * 3072, 0);
    expand_w_kernel<<<(NLAYER * 256  * 1024) / 256, 256>>>(wk, ewqkv, 1024, 256,  (size_t)1536 * 3072, 1024);
    expand_w_kernel<<<(NLAYER * 256  * 1024) / 256, 256>>>(wv, ewqkv, 1024, 256,  (size_t)1536 * 3072, 1280);
    expand_w_kernel<<<(NLAYER * 1024 * 1024) / 256, 256>>>(wo, ewo,   1024, 1024, (size_t)1024 * 3072, 0);
    expand_w_kernel<<<(NLAYER * 4096 * 1024) / 256, 256>>>(w1, ew13,  1024, 4096, (size_t)8192 * 3072, 0);
    expand_w_kernel<<<(NLAYER * 4096 * 1024) / 256, 256>>>(w3, ew13,  1024, 4096, (size_t)8192 * 3072, 4096);
    expand_w_kernel<<<(NLAYER * 1024 * 4096) / 256, 256>>>(w2, ew2,   4096, 1024, (size_t)1024 * 12288, 0);
    expand_w_kernel<<<(VOCAB * 1024) / 256, 256>>>(emb, eemb, 1024, VOCAB, 0, 0);

    rope_init_kernel<<<SEQ, 32>>>();
    embed_kernel<<<TOK, 256>>>(ids, emb);

    for (int l = 0; l < NLAYER; l++) {
        rmsnorm_expand_kernel<<<TOK, 256>>>(h, n1 + (size_t)l * DIM, xne);
        gemm_bf<0><<<dim3(1536 / BN, TOK / BM), 256>>>(
            xne, ewqkv + (size_t)l * 1536 * 3072, nullptr, qkv, 1536, 3072);
        rope_kernel<<<(TOK * NHEAD * 32) / 256, 256>>>(qkv, NHEAD, 0);
        rope_kernel<<<(TOK * KVHEAD * 32) / 256, 256>>>(qkv, KVHEAD, 1024);
        attn_kernel<<<dim3(SEQ / 64, NHEAD, BATCH), 64>>>(qkv, atte);
        gemm_bf<1><<<dim3(1024 / BN, TOK / BM), 256>>>(
            atte, ewo + (size_t)l * 1024 * 3072, h, h, 1024, 3072);
        rmsnorm_expand_kernel<<<TOK, 256>>>(h, n2 + (size_t)l * DIM, xne);
        gemm_bf<0><<<dim3(8192 / BN, TOK / BM), 256>>>(
            xne, ew13 + (size_t)l * 8192 * 3072, nullptr, f13, 8192, 3072);
        swiglu_expand_kernel<<<(TOK * FF) / 256, 256>>>();
        gemm_bf<1><<<dim3(1024 / BN, TOK / BM), 256>>>(
            f1e, ew2 + (size_t)l * 1024 * 12288, h, h, 1024, 12288);
    }
    rmsnorm_expand_kernel<<<TOK, 256>>>(h, fnw, xne);
    gemm_bf<0><<<dim3(VOCAB / BN, TOK / BM), 256>>>(
        xne, eemb, nullptr, out, VOCAB, 3072);
}

// round 11
// speedup vs baseline: 1.1029x; 1.1029x over previous
#include <cuda_runtime.h>
#include <cuda_bf16.h>
#include <math.h>
#include <stdint.h>

#define SEQ    2048
#define BATCH  2
#define TOK    4096
#define DIM    1024
#define NHEAD  16
#define KVHEAD 4
#define HDIM   64
#define NLAYER 8
#define FF     4096
#define VOCAB  32000

typedef __nv_bfloat16 bf16;

// ---------------- scratch ----------------
__device__ float g_h   [TOK * DIM];
__device__ float g_qkv [TOK * 1536];          // [q(1024)|k(256)|v(256)]
__device__ float g_f13 [TOK * 8192];          // [f1(4096)|f3(4096)]
__device__ float g_cos [SEQ * 32];
__device__ float g_sin [SEQ * 32];
// expanded bf16 activations (A-operand: [hi|hi|lo])
__device__ bf16 g_xne [TOK * 3072];
__device__ bf16 g_atte[TOK * 3072];
__device__ bf16 g_f1e [TOK * 12288];
// expanded bf16 weights (B-operand: [hi|lo|hi])
__device__ bf16 e_wqkv[NLAYER * 1536 * 3072];
__device__ bf16 e_wo  [NLAYER * 1024 * 3072];
__device__ bf16 e_w13 [NLAYER * 8192 * 3072];
__device__ bf16 e_w2  [NLAYER * 1024 * 12288];
__device__ bf16 e_emb [VOCAB * 3072];

__device__ __forceinline__ void split2(float x, bf16& hi, bf16& lo) {
    hi = __float2bfloat16_rn(x);
    lo = __float2bfloat16_rn(x - __bfloat162float(hi));
}

// ------- weight expansion, 8 elems/thread: rows = [hi | lo | hi] -------
__global__ void expand_w_kernel(const float* __restrict__ in, bf16* __restrict__ out,
                                int K, int rows_pl, size_t lstride, int row_off) {
    size_t idx = ((size_t)blockIdx.x * 256 + threadIdx.x) * 8;
    size_t rt = idx / K;
    int k  = (int)(idx % K);
    int l  = (int)(rt / rows_pl);
    int r  = (int)(rt % rows_pl);
    float4 x0 = *(const float4*)(in + idx);
    float4 x1 = *(const float4*)(in + idx + 4);
    float xs[8] = {x0.x, x0.y, x0.z, x0.w, x1.x, x1.y, x1.z, x1.w};
    bf16 hi[8], lo[8];
    #pragma unroll
    for (int i = 0; i < 8; i++) split2(xs[i], hi[i], lo[i]);
    bf16* o = out + (size_t)l * lstride + (size_t)(row_off + r) * (3 * K);
    *(uint4*)(o + k)         = *(uint4*)hi;
    *(uint4*)(o + K + k)     = *(uint4*)lo;
    *(uint4*)(o + 2 * K + k) = *(uint4*)hi;
}

// ---------------- RoPE tables ----------------
__global__ void rope_init_kernel() {
    int t = blockIdx.x, j = threadIdx.x;
    double inv   = pow(10000.0, -(2.0 * j) / 64.0);
    double r     = 81920.0 * inv / (2.0 * M_PI);
    double gamma = (r - 1.0) / 31.0;
    gamma = gamma < 0.0 ? 0.0 : (gamma > 1.0 ? 1.0 : gamma);
    double inv2  = inv * ((1.0 - gamma) / 40.0 + gamma);
    double c     = sqrt(0.1 * log(40.0) + 1.0);
    double ang   = (double)t * inv2 / c;
    g_cos[t * 32 + j] = (float)cos(ang);
    g_sin[t * 32 + j] = (float)sin(ang);
}

__global__ void embed_kernel(const int* __restrict__ ids, const float* __restrict__ emb) {
    int t = blockIdx.x;
    const float* src = emb + (size_t)ids[t] * DIM;
    float* dst = g_h + (size_t)t * DIM;
    for (int d = threadIdx.x; d < DIM; d += blockDim.x) dst[d] = src[d];
}

// ---------------- rmsnorm -> expanded bf16 [hi|hi|lo] ----------------
__global__ __launch_bounds__(256) void rmsnorm_expand_kernel(
    const float* __restrict__ x, const float* __restrict__ w, bf16* __restrict__ o) {
    int row = blockIdx.x, tid = threadIdx.x;
    const float* xr = x + (size_t)row * DIM;
    float s = 0.f;
    for (int d = tid; d < DIM; d += 256) { float v = xr[d]; s += v * v; }
    #pragma unroll
    for (int off = 16; off; off >>= 1) s += __shfl_xor_sync(0xffffffffu, s, off);
    __shared__ float red[8]; __shared__ float rsv;
    if ((tid & 31) == 0) red[tid >> 5] = s;
    __syncthreads();
    if (tid == 0) {
        float t = 0.f;
        #pragma unroll
        for (int i = 0; i < 8; i++) t += red[i];
        rsv = rsqrtf(t / (float)DIM + 1e-6f);
    }
    __syncthreads();
    float rs = rsv;
    bf16* orow = o + (size_t)row * 3072;
    #pragma unroll
    for (int i = 0; i < 2; i++) {
        int d = 2 * (tid + i * 256);
        float2 xv = *(const float2*)(xr + d);
        float2 wv = *(const float2*)(w + d);
        float y0 = xv.x * rs * wv.x, y1 = xv.y * rs * wv.y;
        bf16 h0, l0, h1, l1;
        split2(y0, h0, l0); split2(y1, h1, l1);
        *(__nv_bfloat162*)(orow + d)        = __nv_bfloat162(h0, h1);
        *(__nv_bfloat162*)(orow + 1024 + d) = __nv_bfloat162(h0, h1);
        *(__nv_bfloat162*)(orow + 2048 + d) = __nv_bfloat162(l0, l1);
    }
}

// ================= bf16 tensor-core GEMM v3 (BK=64) =================
// C[M,N](f32) = Ae[M,K'](bf16) @ We[N,K'](bf16)^T (+R)
// CTA tile 128x256, BK=64 bf16 (128B rows, full SW128 swizzle), 256 thr,
// warp grid 2(M)x4(N), warp tile 64x64 = 4x8 m16n8k16, 2-stage cp.async.
#define BM 128
#define BN 256
#define BKE 64
#define A_BYTES (BM * BKE * 2)             // 16384
#define B_BYTES (BN * BKE * 2)             // 32768
#define STAGE_BYTES (A_BYTES + B_BYTES)    // 49152
#define SMEM_DYN (2 * STAGE_BYTES)         // 98304

#define CP_ASYNC16(dst, src) \
    asm volatile("cp.async.cg.shared.global [%0], [%1], 16;" :: "r"(dst), "l"(src))
#define CP_COMMIT()  asm volatile("cp.async.commit_group;")
#define CP_WAIT1()   asm volatile("cp.async.wait_group 1;")
#define LDSM_X4(r0, r1, r2, r3, addr) \
    asm volatile("ldmatrix.sync.aligned.m8n8.x4.shared.b16 {%0,%1,%2,%3}, [%4];" \
        : "=r"(r0), "=r"(r1), "=r"(r2), "=r"(r3) : "r"(addr))
#define MMA_BF16(c, a0, a1, a2, a3, b0, b1) \
    asm volatile("mma.sync.aligned.m16n8k16.row.col.f32.bf16.bf16.f32 " \
        "{%0,%1,%2,%3}, {%4,%5,%6,%7}, {%8,%9}, {%0,%1,%2,%3};" \
        : "+f"(c[0]), "+f"(c[1]), "+f"(c[2]), "+f"(c[3]) \
        : "r"(a0), "r"(a1), "r"(a2), "r"(a3), "r"(b0), "r"(b1))

template <int RES>
__global__ __launch_bounds__(256) void gemm_bf(
    const bf16* __restrict__ A, const bf16* __restrict__ W,
    const float* __restrict__ R, float* __restrict__ C, int N, int K) {
    extern __shared__ __align__(16) char smem[];
    const int tid  = threadIdx.x;
    const int lane = tid & 31;
    const int wid  = tid >> 5;
    const int wm   = wid >> 2;
    const int wn   = wid & 3;
    const int bm   = blockIdx.y * BM;
    const int bn   = blockIdx.x * BN;
    const uint32_t smem_u = (uint32_t)__cvta_generic_to_shared(smem);

    // ---- loader: stage = 3072 granules (16B); 12 per thread ----
    // granule g: row = g>>3, col c = g&7; smem off = row*128 + (c^(row&7))*16
    const int lrow = tid >> 3;          // base rows: A uses 32 rows/iter pass
    const int lcol = tid & 7;
    // A: 1024 granules = 4 iters of 256
    const bf16* AgBase = A + (size_t)bm * K;
    const bf16* WgBase = W + (size_t)bn * K;

    // ---- fragment addressing ----
    const int flr = lane & 15;
    const int fhi = lane >> 4;          // 0/1
    int aRow[4], aXor[4];
    #pragma unroll
    for (int i = 0; i < 4; i++) {
        aRow[i] = wm * 64 + i * 16 + flr;
        aXor[i] = aRow[i] & 7;
    }
    const int bkf = (lane >> 3) & 1;
    int bRow[4], bXor[4];
    #pragma unroll
    for (int p = 0; p < 4; p++) {
        bRow[p] = wn * 64 + (lane & 7) + fhi * 8 + p * 16;
        bXor[p] = bRow[p] & 7;
    }

    float acc[4][8][4];
    #pragma unroll
    for (int i = 0; i < 4; i++)
        #pragma unroll
        for (int j = 0; j < 8; j++)
            #pragma unroll
            for (int q = 0; q < 4; q++) acc[i][j][q] = 0.f;

    const int nk = K / BKE;

    auto load_stage = [&](int kt) {
        uint32_t base = smem_u + (kt & 1) * STAGE_BYTES;
        int k0 = kt * BKE;
        #pragma unroll
        for (int it = 0; it < 4; it++) {         // A: rows lrow + it*32
            int r = lrow + it * 32;
            uint32_t dst = base + r * 128 + ((lcol ^ (r & 7)) << 4);
            CP_ASYNC16(dst, AgBase + (size_t)r * K + k0 + lcol * 8);
        }
        uint32_t bb = base + A_BYTES;
        #pragma unroll
        for (int it = 0; it < 8; it++) {         // B: rows lrow + it*32
            int r = lrow + it * 32;
            uint32_t dst = bb + r * 128 + ((lcol ^ (r & 7)) << 4);
            CP_ASYNC16(dst, WgBase + (size_t)r * K + k0 + lcol * 8);
        }
    };

    load_stage(0);
    CP_COMMIT();

    for (int kt = 0; kt < nk; kt++) {
        if (kt + 1 < nk) load_stage(kt + 1);
        CP_COMMIT();
        CP_WAIT1();
        __syncthreads();

        uint32_t cbase = smem_u + (kt & 1) * STAGE_BYTES;
        #pragma unroll
        for (int s = 0; s < 4; s++) {
            uint32_t af[4][4];
            #pragma unroll
            for (int i = 0; i < 4; i++) {
                uint32_t addr = cbase + aRow[i] * 128 + (((2 * s + fhi) ^ aXor[i]) << 4);
                LDSM_X4(af[i][0], af[i][1], af[i][2], af[i][3], addr);
            }
            #pragma unroll
            for (int p = 0; p < 4; p++) {
                uint32_t addr = cbase + (uint32_t)A_BYTES + bRow[p] * 128 +
                                (((2 * s + bkf) ^ bXor[p]) << 4);
                uint32_t b0, b1, b2, b3;
                LDSM_X4(b0, b1, b2, b3, addr);
                #pragma unroll
                for (int i = 0; i < 4; i++) {
                    MMA_BF16(acc[i][2 * p],     af[i][0], af[i][1], af[i][2], af[i][3], b0, b1);
                    MMA_BF16(acc[i][2 * p + 1], af[i][0], af[i][1], af[i][2], af[i][3], b2, b3);
                }
            }
        }
        __syncthreads();
    }

    const int gid = lane >> 2, tig = lane & 3;
    #pragma unroll
    for (int i = 0; i < 4; i++) {
        int r0 = bm + wm * 64 + i * 16 + gid;
        #pragma unroll
        for (int j = 0; j < 8; j++) {
            int c0 = bn + wn * 64 + j * 8 + tig * 2;
            size_t o0 = (size_t)r0 * N + c0;
            size_t o1 = o0 + (size_t)8 * N;
            float2 v0 = make_float2(acc[i][j][0], acc[i][j][1]);
            float2 v1 = make_float2(acc[i][j][2], acc[i][j][3]);
            if (RES) {
                float2 ra = *(const float2*)(R + o0);
                float2 rb = *(const float2*)(R + o1);
                v0.x += ra.x; v0.y += ra.y; v1.x += rb.x; v1.y += rb.y;
            }
            *(float2*)(C + o0) = v0;
            *(float2*)(C + o1) = v1;
        }
    }
}

// ---------------- RoPE on qkv slab ----------------
__global__ void rope_kernel(float* __restrict__ x, int nheads, int off) {
    int idx = blockIdx.x * 256 + threadIdx.x;
    int i  = idx & 31;
    int hh = (idx >> 5) % nheads;
    int t  = idx / (32 * nheads);
    int s  = t & (SEQ - 1);
    float c  = g_cos[s * 32 + i];
    float sn = g_sin[s * 32 + i];
    float* p = x + (size_t)t * 1536 + off + hh * HDIM;
    float x1 = p[i], x2 = p[i + 32];
    p[i]      = x1 * c - x2 * sn;
    p[i + 32] = x2 * c + x1 * sn;
}

// ---------------- causal GQA flash attention (v1: thread-per-query) ---------
__global__ __launch_bounds__(64) void attn_kernel(
    const float* __restrict__ qkv, bf16* __restrict__ oe) {
    __shared__ float Ks[64][64];
    __shared__ float Vs[64][64];
    __shared__ float Ss[64][64];
    int qt = blockIdx.x, h = blockIdx.y, b = blockIdx.z;
    int g = h >> 2;
    int tid = threadIdx.x;
    int qi = qt * 64 + tid;

    const float* qp = qkv + (size_t)(b * SEQ + qi) * 1536 + h * HDIM;
    float qr[64];
    #pragma unroll
    for (int d = 0; d < 64; d += 4) {
        float4 t4 = *(const float4*)(qp + d);
        qr[d] = t4.x * 0.125f; qr[d + 1] = t4.y * 0.125f;
        qr[d + 2] = t4.z * 0.125f; qr[d + 3] = t4.w * 0.125f;
    }
    float m = -1e30f, l = 0.f;
    float acc[64];
    #pragma unroll
    for (int d = 0; d < 64; d++) acc[d] = 0.f;

    for (int j = 0; j <= qt; j++) {
        const float* kp = qkv + (size_t)(b * SEQ + j * 64) * 1536 + 1024 + g * HDIM;
        const float* vp = kp + 256;
        __syncthreads();
        #pragma unroll
        for (int i = 0; i < 16; i++) {
            int idx = i * 64 + tid;
            int r = idx >> 4, c = (idx & 15) * 4;
            *(float4*)&Ks[r][c] = *(const float4*)(kp + (size_t)r * 1536 + c);
            *(float4*)&Vs[r][c] = *(const float4*)(vp + (size_t)r * 1536 + c);
        }
        __syncthreads();
        #pragma unroll
        for (int kk = 0; kk < 64; kk++) {
            float s = 0.f;
            #pragma unroll
            for (int d = 0; d < 64; d += 4) {
                float4 kv = *(const float4*)&Ks[kk][d];
                s += qr[d] * kv.x + qr[d + 1] * kv.y + qr[d + 2] * kv.z + qr[d + 3] * kv.w;
            }
            Ss[kk][tid] = s;
        }
        if (j == qt) {
            for (int kk = tid + 1; kk < 64; kk++) Ss[kk][tid] = -1e30f;
        }
        float tmax = -1e30f;
        #pragma unroll
        for (int kk = 0; kk < 64; kk++) tmax = fmaxf(tmax, Ss[kk][tid]);
        float nm = fmaxf(m, tmax);
        float corr = __expf(m - nm);
        l *= corr;
        #pragma unroll
        for (int d = 0; d < 64; d++) acc[d] *= corr;
        #pragma unroll
        for (int kk = 0; kk < 64; kk++) {
            float p = __expf(Ss[kk][tid] - nm);
            l += p;
            #pragma unroll
            for (int d = 0; d < 64; d += 4) {
                float4 vv = *(const float4*)&Vs[kk][d];
                acc[d]     += p * vv.x; acc[d + 1] += p * vv.y;
                acc[d + 2] += p * vv.z; acc[d + 3] += p * vv.w;
            }
        }
        m = nm;
    }
    float inv = 1.f / l;
    bf16* op = oe + (size_t)(b * SEQ + qi) * 3072 + h * HDIM;
    #pragma unroll
    for (int d = 0; d < 64; d += 2) {
        float y0 = acc[d] * inv, y1 = acc[d + 1] * inv;
        bf16 h0, l0, h1, l1;
        split2(y0, h0, l0); split2(y1, h1, l1);
        *(__nv_bfloat162*)(op + d)        = __nv_bfloat162(h0, h1);
        *(__nv_bfloat162*)(op + 1024 + d) = __nv_bfloat162(h0, h1);
        *(__nv_bfloat162*)(op + 2048 + d) = __nv_bfloat162(l0, l1);
    }
}

// ---------------- SwiGLU -> expanded [hi|hi|lo], 4 elems/thread ----------------
__global__ void swiglu_expand_kernel() {
    int i4 = (blockIdx.x * 256 + threadIdx.x) * 4;   // over TOK*FF
    int t = i4 >> 12, c = i4 & 4095;
    float4 a4 = *(const float4*)(g_f13 + (size_t)t * 8192 + c);
    float4 b4 = *(const float4*)(g_f13 + (size_t)t * 8192 + 4096 + c);
    float as[4] = {a4.x, a4.y, a4.z, a4.w};
    float bs[4] = {b4.x, b4.y, b4.z, b4.w};
    bf16 hi[4], lo[4];
    #pragma unroll
    for (int i = 0; i < 4; i++) {
        float u = (as[i] / (1.f + __expf(-as[i]))) * bs[i];
        split2(u, hi[i], lo[i]);
    }
    bf16* o = g_f1e + (size_t)t * 12288;
    *(uint2*)(o + c)        = *(uint2*)hi;
    *(uint2*)(o + 4096 + c) = *(uint2*)hi;
    *(uint2*)(o + 8192 + c) = *(uint2*)lo;
}

// ---------------- host orchestration ----------------
extern "C" void kernel_launch(void* const* d_in, const int* in_sizes, int n_in,
                              void* d_out, int out_size) {
    const int*   ids = (const int*)d_in[0];
    const float* emb = (const float*)d_in[1];
    const float* wq  = (const float*)d_in[2];
    const float* wk  = (const float*)d_in[3];
    const float* wv  = (const float*)d_in[4];
    const float* wo  = (const float*)d_in[5];
    const float* n1  = (const float*)d_in[6];
    const float* n2  = (const float*)d_in[7];
    const float* w1  = (const float*)d_in[8];
    const float* w2  = (const float*)d_in[9];
    const float* w3  = (const float*)d_in[10];
    const float* fnw = (const float*)d_in[11];
    float* out = (float*)d_out;

    static int smem_set = 0;
    if (!smem_set) {
        cudaFuncSetAttribute(gemm_bf<0>, cudaFuncAttributeMaxDynamicSharedMemorySize, SMEM_DYN);
        cudaFuncSetAttribute(gemm_bf<1>, cudaFuncAttributeMaxDynamicSharedMemorySize, SMEM_DYN);
        smem_set = 1;
    }

    float *h, *qkv, *f13;
    bf16 *xne, *atte, *f1e, *ewqkv, *ewo, *ew13, *ew2, *eemb;
    cudaGetSymbolAddress((void**)&h,     g_h);
    cudaGetSymbolAddress((void**)&qkv,   g_qkv);
    cudaGetSymbolAddress((void**)&f13,   g_f13);
    cudaGetSymbolAddress((void**)&xne,   g_xne);
    cudaGetSymbolAddress((void**)&atte,  g_atte);
    cudaGetSymbolAddress((void**)&f1e,   g_f1e);
    cudaGetSymbolAddress((void**)&ewqkv, e_wqkv);
    cudaGetSymbolAddress((void**)&ewo,   e_wo);
    cudaGetSymbolAddress((void**)&ew13,  e_w13);
    cudaGetSymbolAddress((void**)&ew2,   e_w2);
    cudaGetSymbolAddress((void**)&eemb,  e_emb);

    // ---- expand all weights (bf16 hi/lo triple), 2048 elems/block ----
    expand_w_kernel<<<(NLAYER * 1024 * 1024) / 2048, 256>>>(wq, ewqkv, 1024, 1024, (size_t)1536 * 3072, 0);
    expand_w_kernel<<<(NLAYER * 256  * 1024) / 2048, 256>>>(wk, ewqkv, 1024, 256,  (size_t)1536 * 3072, 1024);
    expand_w_kernel<<<(NLAYER * 256  * 1024) / 2048, 256>>>(wv, ewqkv, 1024, 256,  (size_t)1536 * 3072, 1280);
    expand_w_kernel<<<(NLAYER * 1024 * 1024) / 2048, 256>>>(wo, ewo,   1024, 1024, (size_t)1024 * 3072, 0);
    expand_w_kernel<<<(NLAYER * 4096 * 1024) / 2048, 256>>>(w1, ew13,  1024, 4096, (size_t)8192 * 3072, 0);
    expand_w_kernel<<<(NLAYER * 4096 * 1024) / 2048, 256>>>(w3, ew13,  1024, 4096, (size_t)8192 * 3072, 4096);
    expand_w_kernel<<<(NLAYER * 1024 * 4096) / 2048, 256>>>(w2, ew2,   4096, 1024, (size_t)1024 * 12288, 0);
    expand_w_kernel<<<(VOCAB * 1024) / 2048, 256>>>(emb, eemb, 1024, VOCAB, 0, 0);

    rope_init_kernel<<<SEQ, 32>>>();
    embed_kernel<<<TOK, 256>>>(ids, emb);

    for (int l = 0; l < NLAYER; l++) {
        rmsnorm_expand_kernel<<<TOK, 256>>>(h, n1 + (size_t)l * DIM, xne);
        gemm_bf<0><<<dim3(1536 / BN, TOK / BM), 256, SMEM_DYN>>>(
            xne, ewqkv + (size_t)l * 1536 * 3072, nullptr, qkv, 1536, 3072);
        rope_kernel<<<(TOK * NHEAD * 32) / 256, 256>>>(qkv, NHEAD, 0);
        rope_kernel<<<(TOK * KVHEAD * 32) / 256, 256>>>(qkv, KVHEAD, 1024);
        attn_kernel<<<dim3(SEQ / 64, NHEAD, BATCH), 64>>>(qkv, atte);
        gemm_bf<1><<<dim3(1024 / BN, TOK / BM), 256, SMEM_DYN>>>(
            atte, ewo + (size_t)l * 1024 * 3072, h, h, 1024, 3072);
        rmsnorm_expand_kernel<<<TOK, 256>>>(h, n2 + (size_t)l * DIM, xne);
        gemm_bf<0><<<dim3(8192 / BN, TOK / BM), 256, SMEM_DYN>>>(
            xne, ew13 + (size_t)l * 8192 * 3072, nullptr, f13, 8192, 3072);
        swiglu_expand_kernel<<<(TOK * FF) / 1024, 256>>>();
        gemm_bf<1><<<dim3(1024 / BN, TOK / BM), 256, SMEM_DYN>>>(
            f1e, ew2 + (size_t)l * 1024 * 12288, h, h, 1024, 12288);
    }
    rmsnorm_expand_kernel<<<TOK, 256>>>(h, fnw, xne);
    gemm_bf<0><<<dim3(VOCAB / BN, TOK / BM), 256, SMEM_DYN>>>(
        xne, eemb, nullptr, out, VOCAB, 3072);
}